// round 16
// baseline (speedup 1.0000x reference)
#include <cuda_runtime.h>
#include <cuda_bf16.h>
#include <math.h>
#include <stdint.h>

#define NN    20000
#define EE    160000
#define IND   128
#define HIDD  96
#define NH    6
#define NG    512
#define NCLS  128
#define HD    576
#define QC    1824

#define BM 128
#define BN 96
#define BK 32

// ---------------- scratch (allocation-free) ----------------
__device__ __nv_bfloat16  g_qh[(size_t)NN * HD];       // bf16 q
__device__ __nv_bfloat16  g_kvh[(size_t)NN * 1152];    // bf16 k|v
__device__ float          g_skip[NN * HIDD];
__device__ float          g_h[NN * HIDD];              // fp32 h (GEMM input, tf32 path)
__device__ int   g_src[EE], g_dst[EE], g_srcs[EE];
__device__ int   g_deg[NN], g_rowptr[NN + 1], g_cursor[NN];
__device__ int   g_batch[NN];
__device__ float g_pool[NG * HIDD];
__device__ int   g_cnt[NG];
__device__ float g_gbuf[NG * HIDD];
__device__ float g_wn[NCLS * HIDD];
__device__ int   g_is64;

// ---------------- helpers ----------------
__device__ __forceinline__ void mma8(float* c, const unsigned* a, const unsigned* b) {
    asm volatile(
        "mma.sync.aligned.m16n8k8.row.col.f32.tf32.tf32.f32 "
        "{%0,%1,%2,%3}, {%4,%5,%6,%7}, {%8,%9}, {%0,%1,%2,%3};"
        : "+f"(c[0]), "+f"(c[1]), "+f"(c[2]), "+f"(c[3])
        : "r"(a[0]), "r"(a[1]), "r"(a[2]), "r"(a[3]), "r"(b[0]), "r"(b[1]));
}

__device__ __forceinline__ void cpasync16(void* dst, const void* src, bool pred) {
    unsigned sa = (unsigned)__cvta_generic_to_shared(dst);
    int sz = pred ? 16 : 0;
    asm volatile("cp.async.cg.shared.global [%0], [%1], 16, %2;\n"
                 :: "r"(sa), "l"(src), "r"(sz));
}
#define CP_COMMIT() asm volatile("cp.async.commit_group;\n")
#define CP_WAIT(n)  asm volatile("cp.async.wait_group %0;\n" :: "n"(n))

// ---------------- preprocessing ----------------
__global__ void init_kernel(const unsigned* w) {
    int i = blockIdx.x * blockDim.x + threadIdx.x;
    if (i < NN) g_deg[i] = 0;
    if (blockIdx.x == 0) {
        __shared__ int any;
        if (threadIdx.x == 0) any = 0;
        __syncthreads();
        for (int j = threadIdx.x; j < 2048; j += blockDim.x)
            if (w[2 * j + 1] != 0u) any = 1;
        __syncthreads();
        if (threadIdx.x == 0) g_is64 = (any == 0);
    }
}

__global__ void extract_all(const void* ei, const void* bt) {
    int e = blockIdx.x * blockDim.x + threadIdx.x;
    if (e < EE) {
        int s, d;
        if (g_is64) {
            const long long* p = (const long long*)ei;
            s = (int)p[e]; d = (int)p[EE + e];
        } else {
            const int* p = (const int*)ei;
            s = p[e]; d = p[EE + e];
        }
        g_src[e] = s; g_dst[e] = d;
        atomicAdd(&g_deg[d], 1);
    }
    if (e < NN)
        g_batch[e] = g_is64 ? (int)((const long long*)bt)[e] : ((const int*)bt)[e];
}

__global__ void scan_kernel() {
    const int PER = 20;
    int tid = threadIdx.x, lane = tid & 31, wid = tid >> 5;
    int base = tid * PER;
    int sum = 0;
    int lim = (base < NN) ? min(PER, NN - base) : 0;
    if (lim == PER) {
#pragma unroll
        for (int j = 0; j < 5; j++) {
            int4 v = *(const int4*)&g_deg[base + j * 4];
            sum += v.x + v.y + v.z + v.w;
        }
    } else {
        for (int j = 0; j < lim; j++) sum += g_deg[base + j];
    }
    int v = sum;
#pragma unroll
    for (int off = 1; off < 32; off <<= 1) {
        int t = __shfl_up_sync(0xffffffffu, v, off);
        if (lane >= off) v += t;
    }
    __shared__ int wsum[32];
    if (lane == 31) wsum[wid] = v;
    __syncthreads();
    if (wid == 0) {
        int wv = wsum[lane];
#pragma unroll
        for (int off = 1; off < 32; off <<= 1) {
            int t = __shfl_up_sync(0xffffffffu, wv, off);
            if (lane >= off) wv += t;
        }
        wsum[lane] = wv;
    }
    __syncthreads();
    int excl = v - sum + (wid ? wsum[wid - 1] : 0);
    int run = excl;
    for (int j = 0; j < lim; j++) {
        g_rowptr[base + j] = run;
        g_cursor[base + j] = run;
        run += g_deg[base + j];
    }
    if (tid == 1023) g_rowptr[NN] = excl + sum;
}

__global__ void scatter_kernel() {
    int e = blockIdx.x * blockDim.x + threadIdx.x;
    if (e >= EE) return;
    int d = g_dst[e];
    int pos = atomicAdd(&g_cursor[d], 1);
    g_srcs[pos] = g_src[e];
}

// ---------------- TF32 GEMM (R7/R9 proven 256-thread version) ----------------
__global__ void __launch_bounds__(256) gemm_tc(
        const float* __restrict__ A, int K,
        const float* __restrict__ Wq, const float* __restrict__ Wk,
        const float* __restrict__ Wv, const float* __restrict__ Ws,
        const float* __restrict__ bq, const float* __restrict__ bk,
        const float* __restrict__ bv, const float* __restrict__ bs) {
    __shared__ __align__(16) float As[2][BM][BK + 4];
    __shared__ __align__(16) float Bs[2][BK][BN + 8];
    int tid = threadIdx.x;
    int m0 = blockIdx.y * BM, n0 = blockIdx.x * BN;

    const float* W; const float* bias; int ldw, nbase, segid;
    if (n0 < 576)       { W = Wq; bias = bq; ldw = 576; nbase = n0;        segid = 0; }
    else if (n0 < 1152) { W = Wk; bias = bk; ldw = 576; nbase = n0 - 576;  segid = 1; }
    else if (n0 < 1728) { W = Wv; bias = bv; ldw = 576; nbase = n0 - 1152; segid = 2; }
    else                { W = Ws; bias = bs; ldw = 96;  nbase = 0;         segid = 3; }

    int wid = tid >> 5, lane = tid & 31;
    int wm = wid & 3, wn = wid >> 2;
    int g = lane >> 2, t = lane & 3;
    int c4 = tid & 7, rbase = tid >> 3;

    float acc[2][6][4];
#pragma unroll
    for (int i = 0; i < 2; i++)
#pragma unroll
        for (int j = 0; j < 6; j++)
#pragma unroll
            for (int q = 0; q < 4; q++) acc[i][j][q] = 0.f;

    int KT = K / BK;

#define LOAD_TILES(ST, K0)                                                        \
    do {                                                                          \
        _Pragma("unroll")                                                         \
        for (int i_ = 0; i_ < 4; i_++) {                                          \
            int m_ = rbase + i_ * 32;                                             \
            int gm_ = m0 + m_;                                                    \
            cpasync16(&As[ST][m_][c4 * 4], A + (size_t)gm_ * K + (K0) + c4 * 4,   \
                      gm_ < NN);                                                  \
        }                                                                         \
        _Pragma("unroll")                                                         \
        for (int i_ = 0; i_ < 3; i_++) {                                          \
            int idx_ = tid + i_ * 256;                                            \
            int kk_ = idx_ / 24, cc_ = idx_ - kk_ * 24;                           \
            cpasync16(&Bs[ST][kk_][cc_ * 4],                                      \
                      W + (size_t)((K0) + kk_) * ldw + nbase + cc_ * 4, true);    \
        }                                                                         \
    } while (0)

    LOAD_TILES(0, 0);
    CP_COMMIT();

    for (int kt = 0; kt < KT; kt++) {
        int cur = kt & 1;
        if (kt + 1 < KT) {
            LOAD_TILES(cur ^ 1, (kt + 1) * BK);
            CP_COMMIT();
            CP_WAIT(1);
        } else {
            CP_WAIT(0);
        }
        __syncthreads();
#pragma unroll
        for (int ks = 0; ks < BK; ks += 8) {
            unsigned af[2][4], bf[6][2];
#pragma unroll
            for (int mt = 0; mt < 2; mt++) {
                int mm = wm * 32 + mt * 16 + g;
                af[mt][0] = __float_as_uint(As[cur][mm][ks + t]);
                af[mt][1] = __float_as_uint(As[cur][mm + 8][ks + t]);
                af[mt][2] = __float_as_uint(As[cur][mm][ks + t + 4]);
                af[mt][3] = __float_as_uint(As[cur][mm + 8][ks + t + 4]);
            }
#pragma unroll
            for (int nt = 0; nt < 6; nt++) {
                int nn2 = wn * 48 + nt * 8 + g;
                bf[nt][0] = __float_as_uint(Bs[cur][ks + t][nn2]);
                bf[nt][1] = __float_as_uint(Bs[cur][ks + t + 4][nn2]);
            }
#pragma unroll
            for (int mt = 0; mt < 2; mt++)
#pragma unroll
                for (int nt = 0; nt < 6; nt++)
                    mma8(acc[mt][nt], af[mt], bf[nt]);
        }
        __syncthreads();
    }

#pragma unroll
    for (int mt = 0; mt < 2; mt++) {
        int r0 = m0 + wm * 32 + mt * 16 + g;
#pragma unroll
        for (int nt = 0; nt < 6; nt++) {
            int lc = nbase + wn * 48 + nt * 8 + 2 * t;
            float b0 = bias[lc], b1 = bias[lc + 1];
#pragma unroll
            for (int half = 0; half < 2; half++) {
                int r = r0 + half * 8;
                if (r >= NN) continue;
                float x0 = acc[mt][nt][2 * half] + b0;
                float x1 = acc[mt][nt][2 * half + 1] + b1;
                if (segid == 0) {
                    *(__nv_bfloat162*)(g_qh + (size_t)r * HD + lc) =
                        __float22bfloat162_rn(make_float2(x0, x1));
                } else if (segid == 3) {
                    *(float2*)(g_skip + (size_t)r * HIDD + lc) = make_float2(x0, x1);
                } else {
                    size_t off = (size_t)r * 1152 + (segid == 2 ? 576 : 0) + lc;
                    *(__nv_bfloat162*)(g_kvh + off) =
                        __float22bfloat162_rn(make_float2(x0, x1));
                }
            }
        }
    }
#undef LOAD_TILES
}

// ---------------- fused attention: 4 groups of 8 lanes per warp, smem merge ----------------
__global__ void __launch_bounds__(192) attn_fused() {
    __shared__ float sm[NH][4], ss[NH][4];
    __shared__ float sacc[NH][4][HIDD];    // 9216 B
    __shared__ float wsc[NH][4];
    __shared__ float sinv[NH];
    int n = blockIdx.x;
    int wid = threadIdx.x >> 5, lane = threadIdx.x & 31;
    int grp = lane >> 3, sub = lane & 7;
    int hb = wid * 48 + sub * 6;           // lane's first bf162 (12 dims per lane)
    const __nv_bfloat162* kv2 = (const __nv_bfloat162*)g_kvh;   // row stride 576
    const __nv_bfloat162* q2  = (const __nv_bfloat162*)g_qh;    // row stride 288

    float q[12];
#pragma unroll
    for (int j = 0; j < 6; j++) {
        float2 t = __bfloat1622float2(__ldg(q2 + (size_t)n * 288 + hb + j));
        q[2*j] = t.x; q[2*j+1] = t.y;
    }
    int beg = g_rowptr[n], end = g_rowptr[n + 1];
    float m = -INFINITY, s = 0.f;
    float acc[12];
#pragma unroll
    for (int j = 0; j < 12; j++) acc[j] = 0.f;
    const float SC = 0.10206207261596577f;   // 1/sqrt(96)

    for (int i = beg; i < end; i += 4) {
        int e = i + grp;
        bool valid = (e < end);
        int sv = __ldg(&g_srcs[valid ? e : beg]);
        const __nv_bfloat162* kr = kv2 + (size_t)sv * 576 + hb;
        float k[12], v[12];
#pragma unroll
        for (int j = 0; j < 6; j++) {
            float2 a = __bfloat1622float2(__ldg(kr + j));
            k[2*j] = a.x; k[2*j+1] = a.y;
        }
#pragma unroll
        for (int j = 0; j < 6; j++) {
            float2 a = __bfloat1622float2(__ldg(kr + 288 + j));
            v[2*j] = a.x; v[2*j+1] = a.y;
        }
        float p = 0.f;
#pragma unroll
        for (int j = 0; j < 12; j++) p += q[j] * k[j];
        p += __shfl_xor_sync(0xffffffffu, p, 4);
        p += __shfl_xor_sync(0xffffffffu, p, 2);
        p += __shfl_xor_sync(0xffffffffu, p, 1);
        // invalid edges get logit -3e38: weight ~0 unless whole group is invalid,
        // in which case the polluted state is killed at the per-head merge below.
        float al = valid ? p * SC : -3.0e38f;
        float mn = fmaxf(m, al);             // always finite inside the loop
        float corr = __expf(m - mn);         // first iter: exp(-inf) = 0
        float w = __expf(al - mn);
#pragma unroll
        for (int j = 0; j < 12; j++) acc[j] = acc[j] * corr + w * v[j];
        s = s * corr + w;
        m = mn;
    }
    if (sub == 0) { sm[wid][grp] = m; ss[wid][grp] = s; }
#pragma unroll
    for (int j = 0; j < 12; j++) sacc[wid][grp][sub * 12 + j] = acc[j];
    __syncthreads();
    // per-head merge coefficients (threads 0..5)
    if (threadIdx.x < NH) {
        int h = threadIdx.x;
        float m0 = sm[h][0], m1 = sm[h][1], m2 = sm[h][2], m3 = sm[h][3];
        float M = fmaxf(fmaxf(m0, m1), fmaxf(m2, m3));
        if (M == -INFINITY) {                // deg-0 node
            wsc[h][0] = wsc[h][1] = wsc[h][2] = wsc[h][3] = 0.f;
            sinv[h] = 0.f;
        } else {
            float w0 = __expf(m0 - M), w1 = __expf(m1 - M);
            float w2 = __expf(m2 - M), w3 = __expf(m3 - M);
            float S = ss[h][0]*w0 + ss[h][1]*w1 + ss[h][2]*w2 + ss[h][3]*w3;
            wsc[h][0] = w0; wsc[h][1] = w1; wsc[h][2] = w2; wsc[h][3] = w3;
            sinv[h] = (S > 0.f) ? 1.f / (6.f * S) : 0.f;   // head mean folded in
        }
    }
    __syncthreads();
    if (threadIdx.x < HIDD) {
        int d = threadIdx.x;
        float out = 0.f;
#pragma unroll
        for (int h = 0; h < NH; h++) {
            float t = sacc[h][0][d]*wsc[h][0] + sacc[h][1][d]*wsc[h][1]
                    + sacc[h][2][d]*wsc[h][2] + sacc[h][3][d]*wsc[h][3];
            out += t * sinv[h];
        }
        out += g_skip[n * HIDD + d];
        g_h[n * HIDD + d] = fmaxf(out, 0.f);
    }
}

// ---------------- pooling + head ----------------
__global__ void zero_pool_kernel() {
    int i = blockIdx.x * blockDim.x + threadIdx.x;
    if (i < NG * HIDD) g_pool[i] = 0.f;
    if (i < NG) g_cnt[i] = 0;
}

__global__ void pool_kernel() {
    int i = blockIdx.x * blockDim.x + threadIdx.x;
    if (i >= NN * HIDD) return;
    int n = i / HIDD, d = i - n * HIDD;
    atomicAdd(&g_pool[g_batch[n] * HIDD + d], g_h[i]);
    if (d == 0) atomicAdd(&g_cnt[g_batch[n]], 1);
}

__global__ void head_kernel(const float* __restrict__ fc1w, const float* __restrict__ fc1b,
                            const float* __restrict__ fc2w, const float* __restrict__ fc2b) {
    int b = blockIdx.x, d = threadIdx.x;
    __shared__ float sg[96], st[96];
    __shared__ float snorm;
    float c = fmaxf((float)g_cnt[b], 1.f);
    sg[d] = g_pool[b * HIDD + d] / c;
    __syncthreads();
    float acc = fc1b[d];
    for (int i = 0; i < HIDD; i++) acc += sg[i] * fc1w[i * HIDD + d];
    st[d] = fmaxf(acc, 0.f);
    __syncthreads();
    acc = fc2b[d];
    for (int i = 0; i < HIDD; i++) acc += st[i] * fc2w[i * HIDD + d];
    float o = fmaxf(acc, 0.f);
    sg[d] = o * o;
    __syncthreads();
    if (d == 0) {
        float ss = 0.f;
        for (int i = 0; i < HIDD; i++) ss += sg[i];
        snorm = sqrtf(ss) + 1e-12f;
    }
    __syncthreads();
    g_gbuf[b * HIDD + d] = o / snorm;
}

__global__ void wn_kernel(const float* __restrict__ arcw) {
    int cIdx = blockIdx.x, d = threadIdx.x;
    __shared__ float sq[96];
    __shared__ float sn;
    float w = arcw[cIdx * HIDD + d];
    sq[d] = w * w;
    __syncthreads();
    if (d == 0) {
        float ss = 0.f;
        for (int i = 0; i < HIDD; i++) ss += sq[i];
        sn = sqrtf(ss) + 1e-12f;
    }
    __syncthreads();
    g_wn[cIdx * HIDD + d] = w / sn;
}

__global__ void out_kernel(float* __restrict__ out) {
    int t = blockIdx.x * blockDim.x + threadIdx.x;
    if (t >= NG * NCLS) return;
    int g = t / NCLS, c = t - g * NCLS;
    float acc = 0.f;
    for (int d = 0; d < HIDD; d++) acc += g_gbuf[g * HIDD + d] * g_wn[c * HIDD + d];
    out[t] = 30.f * acc;
}

// ---------------- driver ----------------
extern "C" void kernel_launch(void* const* d_in, const int* in_sizes, int n_in,
                              void* d_out, int out_size) {
    const float* x    = (const float*)d_in[0];
    const void*  ei   = d_in[1];
    const void*  bt   = d_in[2];
    const float* Wq1  = (const float*)d_in[3];
    const float* bq1  = (const float*)d_in[4];
    const float* Wk1  = (const float*)d_in[5];
    const float* bk1  = (const float*)d_in[6];
    const float* Wv1  = (const float*)d_in[7];
    const float* bv1  = (const float*)d_in[8];
    const float* Ws1  = (const float*)d_in[9];
    const float* bs1  = (const float*)d_in[10];
    const float* Wq_r = (const float*)d_in[11];
    const float* bq_r = (const float*)d_in[12];
    const float* Wk_r = (const float*)d_in[13];
    const float* bk_r = (const float*)d_in[14];
    const float* Wv_r = (const float*)d_in[15];
    const float* bv_r = (const float*)d_in[16];
    const float* Ws_r = (const float*)d_in[17];
    const float* bs_r = (const float*)d_in[18];
    const float* fc1w = (const float*)d_in[19];
    const float* fc1b = (const float*)d_in[20];
    const float* fc2w = (const float*)d_in[21];
    const float* fc2b = (const float*)d_in[22];
    const float* arcw = (const float*)d_in[23];
    float* out = (float*)d_out;

    void* hAddr = nullptr;
    cudaGetSymbolAddress(&hAddr, g_h);
    const float* hbuf = (const float*)hAddr;

    dim3 ggrid(QC / BN, (NN + BM - 1) / BM);   // 19 x 157

    init_kernel<<<(NN + 255) / 256, 256>>>((const unsigned*)ei);
    extract_all<<<(EE + 255) / 256, 256>>>(ei, bt);
    scan_kernel<<<1, 1024>>>();
    gemm_tc<<<ggrid, 256>>>(x, IND, Wq1, Wk1, Wv1, Ws1, bq1, bk1, bv1, bs1);  // launch #3 -> ncu
    scatter_kernel<<<(EE + 255) / 256, 256>>>();
    attn_fused<<<NN, 192>>>();

    for (int l = 1; l < 5; l++) {
        int i = l - 1;
        gemm_tc<<<ggrid, 256>>>(hbuf, HIDD,
                                Wq_r + (size_t)i * HIDD * HD, Wk_r + (size_t)i * HIDD * HD,
                                Wv_r + (size_t)i * HIDD * HD, Ws_r + (size_t)i * HIDD * HIDD,
                                bq_r + (size_t)i * HD, bk_r + (size_t)i * HD,
                                bv_r + (size_t)i * HD, bs_r + (size_t)i * HIDD);
        attn_fused<<<NN, 192>>>();
    }

    zero_pool_kernel<<<(NG * HIDD + 255) / 256, 256>>>();
    pool_kernel<<<(NN * HIDD + 255) / 256, 256>>>();
    head_kernel<<<NG, HIDD>>>(fc1w, fc1b, fc2w, fc2b);
    wn_kernel<<<NCLS, HIDD>>>(arcw);
    out_kernel<<<(NG * NCLS + 255) / 256, 256>>>(out);
}

// round 17
// speedup vs baseline: 1.2168x; 1.2168x over previous
#include <cuda_runtime.h>
#include <cuda_bf16.h>
#include <math.h>
#include <stdint.h>

#define NN    20000
#define EE    160000
#define IND   128
#define HIDD  96
#define NH    6
#define NG    512
#define NCLS  128
#define HD    576
#define QC    1824

#define BM 128
#define BN 96
#define BK 32

// ---------------- scratch (allocation-free) ----------------
__device__ __nv_bfloat16  g_qh[(size_t)NN * HD];       // bf16 q
__device__ __nv_bfloat16  g_kvh[(size_t)NN * 1152];    // bf16 k|v
__device__ float          g_skip[NN * HIDD];
__device__ float          g_h[NN * HIDD];              // fp32 h (GEMM input)
__device__ float          g_Wtf[1824 * 128 + 4 * 1824 * 96];  // fp32 W^T, k pair-permuted
__device__ int   g_src[EE], g_dst[EE], g_srcs[EE];
__device__ int   g_deg[NN], g_rowptr[NN + 1], g_cursor[NN];
__device__ int   g_batch[NN];
__device__ float g_pool[NG * HIDD];
__device__ int   g_cnt[NG];
__device__ float g_gbuf[NG * HIDD];
__device__ float g_wn[NCLS * HIDD];
__device__ int   g_is64;

// ---------------- helpers ----------------
__device__ __forceinline__ void mma8(float* c, const unsigned* a, const unsigned* b) {
    asm volatile(
        "mma.sync.aligned.m16n8k8.row.col.f32.tf32.tf32.f32 "
        "{%0,%1,%2,%3}, {%4,%5,%6,%7}, {%8,%9}, {%0,%1,%2,%3};"
        : "+f"(c[0]), "+f"(c[1]), "+f"(c[2]), "+f"(c[3])
        : "r"(a[0]), "r"(a[1]), "r"(a[2]), "r"(a[3]), "r"(b[0]), "r"(b[1]));
}

__device__ __forceinline__ void cpasync16(void* dst, const void* src, bool pred) {
    unsigned sa = (unsigned)__cvta_generic_to_shared(dst);
    int sz = pred ? 16 : 0;
    asm volatile("cp.async.cg.shared.global [%0], [%1], 16, %2;\n"
                 :: "r"(sa), "l"(src), "r"(sz));
}
#define CP_COMMIT() asm volatile("cp.async.commit_group;\n")
#define CP_WAIT(n)  asm volatile("cp.async.wait_group %0;\n" :: "n"(n))

// load 6 bf16 (3 x bf162) -> 6 floats
__device__ __forceinline__ void ld6(const __nv_bfloat162* p, float* f) {
    float2 a = __bfloat1622float2(__ldg(p));
    float2 b = __bfloat1622float2(__ldg(p + 1));
    float2 c = __bfloat1622float2(__ldg(p + 2));
    f[0] = a.x; f[1] = a.y; f[2] = b.x; f[3] = b.y; f[4] = c.x; f[5] = c.y;
}

__device__ __forceinline__ float dot6(const float* q, const __nv_bfloat162* p) {
    float k[6];
    ld6(p, k);
    return q[0]*k[0] + q[1]*k[1] + q[2]*k[2] + q[3]*k[3] + q[4]*k[4] + q[5]*k[5];
}

// ---------------- weight transpose (fp32, k pair-permuted) ----------------
__global__ void wprep(const float* __restrict__ Wq1, const float* __restrict__ Wk1,
                      const float* __restrict__ Wv1, const float* __restrict__ Ws1,
                      const float* __restrict__ Wq_r, const float* __restrict__ Wk_r,
                      const float* __restrict__ Wv_r, const float* __restrict__ Ws_r) {
    int l = blockIdx.z;
    int K = l ? HIDD : IND;
    if (blockIdx.y * 32 >= K) return;
    const float *Wq, *Wk, *Wv, *Ws;
    if (l == 0) { Wq = Wq1; Wk = Wk1; Wv = Wv1; Ws = Ws1; }
    else {
        size_t o = (size_t)(l - 1) * HIDD * HD, o2 = (size_t)(l - 1) * HIDD * HIDD;
        Wq = Wq_r + o; Wk = Wk_r + o; Wv = Wv_r + o; Ws = Ws_r + o2;
    }
    __shared__ float tile[32][33];
    int tx = threadIdx.x, ty = threadIdx.y;   // (32, 8)
#pragma unroll
    for (int j = 0; j < 4; j++) {
        int k = blockIdx.y * 32 + ty + j * 8;
        int n = blockIdx.x * 32 + tx;
        float v = 0.f;
        if (k < K)
            v = (n < 576)  ? Wq[k * 576 + n]
              : (n < 1152) ? Wk[k * 576 + n - 576]
              : (n < 1728) ? Wv[k * 576 + n - 1152]
                           : Ws[k * 96 + n - 1728];
        tile[ty + j * 8][tx] = v;
    }
    __syncthreads();
    size_t base = (l == 0) ? 0 : (size_t)1824 * 128 + (size_t)(l - 1) * 1824 * 96;
#pragma unroll
    for (int j = 0; j < 4; j++) {
        int n = blockIdx.x * 32 + ty + j * 8;
        int k = blockIdx.y * 32 + tx;
        if (k < K) {
            int kp = (k & ~7) | (2 * (k & 3) + ((k >> 2) & 1));
            g_Wtf[base + (size_t)n * K + kp] = tile[tx][ty + j * 8];
        }
    }
}

// ---------------- side-stream preprocessing ----------------
// zero deg/pool/cnt + dtype detect (grid covers NG*HIDD = 49152)
__global__ void init_kernel(const unsigned* w) {
    int i = blockIdx.x * blockDim.x + threadIdx.x;
    if (i < NN) g_deg[i] = 0;
    if (i < NG * HIDD) g_pool[i] = 0.f;
    if (i < NG) g_cnt[i] = 0;
    if (blockIdx.x == 0) {
        __shared__ int any;
        if (threadIdx.x == 0) any = 0;
        __syncthreads();
        for (int j = threadIdx.x; j < 2048; j += blockDim.x)
            if (w[2 * j + 1] != 0u) any = 1;
        __syncthreads();
        if (threadIdx.x == 0) g_is64 = (any == 0);
    }
}

__global__ void extract_all(const void* ei, const void* bt) {
    int e = blockIdx.x * blockDim.x + threadIdx.x;
    if (e < EE) {
        int s, d;
        if (g_is64) {
            const long long* p = (const long long*)ei;
            s = (int)p[e]; d = (int)p[EE + e];
        } else {
            const int* p = (const int*)ei;
            s = p[e]; d = p[EE + e];
        }
        g_src[e] = s; g_dst[e] = d;
        atomicAdd(&g_deg[d], 1);
    }
    if (e < NN) {
        int b = g_is64 ? (int)((const long long*)bt)[e] : ((const int*)bt)[e];
        g_batch[e] = b;
        atomicAdd(&g_cnt[b], 1);
    }
}

__global__ void scan_kernel() {
    const int PER = 20;
    int tid = threadIdx.x, lane = tid & 31, wid = tid >> 5;
    int base = tid * PER;
    int sum = 0;
    int lim = (base < NN) ? min(PER, NN - base) : 0;
    if (lim == PER) {
#pragma unroll
        for (int j = 0; j < 5; j++) {
            int4 v = *(const int4*)&g_deg[base + j * 4];
            sum += v.x + v.y + v.z + v.w;
        }
    } else {
        for (int j = 0; j < lim; j++) sum += g_deg[base + j];
    }
    int v = sum;
#pragma unroll
    for (int off = 1; off < 32; off <<= 1) {
        int t = __shfl_up_sync(0xffffffffu, v, off);
        if (lane >= off) v += t;
    }
    __shared__ int wsum[32];
    if (lane == 31) wsum[wid] = v;
    __syncthreads();
    if (wid == 0) {
        int wv = wsum[lane];
#pragma unroll
        for (int off = 1; off < 32; off <<= 1) {
            int t = __shfl_up_sync(0xffffffffu, wv, off);
            if (lane >= off) wv += t;
        }
        wsum[lane] = wv;
    }
    __syncthreads();
    int excl = v - sum + (wid ? wsum[wid - 1] : 0);
    int run = excl;
    for (int j = 0; j < lim; j++) {
        g_rowptr[base + j] = run;
        g_cursor[base + j] = run;
        run += g_deg[base + j];
    }
    if (tid == 1023) g_rowptr[NN] = excl + sum;
}

__global__ void scatter_kernel() {
    int e = blockIdx.x * blockDim.x + threadIdx.x;
    if (e >= EE) return;
    int d = g_dst[e];
    int pos = atomicAdd(&g_cursor[d], 1);
    g_srcs[pos] = g_src[e];
}

// ---------------- TF32 GEMM: 128 threads, 4 warps, warp tile 64x48 (R11 proven) ----------------
__global__ void __launch_bounds__(128, 3) gemm_tc(
        const float* __restrict__ A, int K, const float* __restrict__ Wt,
        const float* __restrict__ bq, const float* __restrict__ bk,
        const float* __restrict__ bv, const float* __restrict__ bs) {
    __shared__ __align__(16) float As[2][BM][36];
    __shared__ __align__(16) float Bs[2][BN][40];
    int tid = threadIdx.x;
    int m0 = blockIdx.y * BM, n0 = blockIdx.x * BN;

    const float* bias; int nbase, segid;
    if (n0 < 576)       { bias = bq; nbase = n0;        segid = 0; }
    else if (n0 < 1152) { bias = bk; nbase = n0 - 576;  segid = 1; }
    else if (n0 < 1728) { bias = bv; nbase = n0 - 1152; segid = 2; }
    else                { bias = bs; nbase = 0;         segid = 3; }

    int wid = tid >> 5, lane = tid & 31;
    int wm = wid & 1, wn = wid >> 1;
    int g = lane >> 2, t = lane & 3;

    float acc[4][6][4];
#pragma unroll
    for (int i = 0; i < 4; i++)
#pragma unroll
        for (int j = 0; j < 6; j++)
#pragma unroll
            for (int q = 0; q < 4; q++) acc[i][j][q] = 0.f;

    int KT = K / BK;

#define LOAD_TILES(ST, K0)                                                        \
    do {                                                                          \
        _Pragma("unroll")                                                         \
        for (int i_ = 0; i_ < 8; i_++) {                                          \
            int ch_ = i_ * 128 + tid;                                             \
            int m_ = ch_ >> 3, c_ = ch_ & 7;                                      \
            int gm_ = m0 + m_;                                                    \
            cpasync16(&As[ST][m_][c_ * 4], A + (size_t)gm_ * K + (K0) + c_ * 4,   \
                      gm_ < NN);                                                  \
        }                                                                         \
        _Pragma("unroll")                                                         \
        for (int i_ = 0; i_ < 6; i_++) {                                          \
            int ch_ = i_ * 128 + tid;                                             \
            int n_ = ch_ >> 3, c_ = ch_ & 7;                                      \
            cpasync16(&Bs[ST][n_][c_ * 4],                                        \
                      Wt + (size_t)(n0 + n_) * K + (K0) + c_ * 4, true);          \
        }                                                                         \
    } while (0)

    LOAD_TILES(0, 0);
    CP_COMMIT();

    for (int kt = 0; kt < KT; kt++) {
        int cur = kt & 1;
        if (kt + 1 < KT) {
            LOAD_TILES(cur ^ 1, (kt + 1) * BK);
            CP_COMMIT();
            CP_WAIT(1);
        } else {
            CP_WAIT(0);
        }
        __syncthreads();
#pragma unroll
        for (int ks = 0; ks < BK; ks += 8) {
            unsigned af[4][4];
            float2 bf[6];
#pragma unroll
            for (int mt = 0; mt < 4; mt++) {
                int mm = wm * 64 + mt * 16 + g;
                af[mt][0] = __float_as_uint(As[cur][mm][ks + t]);
                af[mt][1] = __float_as_uint(As[cur][mm + 8][ks + t]);
                af[mt][2] = __float_as_uint(As[cur][mm][ks + t + 4]);
                af[mt][3] = __float_as_uint(As[cur][mm + 8][ks + t + 4]);
            }
#pragma unroll
            for (int nt = 0; nt < 6; nt++) {
                int nn2 = wn * 48 + nt * 8 + g;
                bf[nt] = *(const float2*)&Bs[cur][nn2][ks + 2 * t];
            }
#pragma unroll
            for (int mt = 0; mt < 4; mt++)
#pragma unroll
                for (int nt = 0; nt < 6; nt++)
                    mma8(acc[mt][nt], af[mt], (const unsigned*)&bf[nt]);
        }
        __syncthreads();
    }

#pragma unroll
    for (int mt = 0; mt < 4; mt++) {
        int r0 = m0 + wm * 64 + mt * 16 + g;
#pragma unroll
        for (int nt = 0; nt < 6; nt++) {
            int lc = nbase + wn * 48 + nt * 8 + 2 * t;
            float b0 = bias[lc], b1 = bias[lc + 1];
#pragma unroll
            for (int half = 0; half < 2; half++) {
                int r = r0 + half * 8;
                if (r >= NN) continue;
                float x0 = acc[mt][nt][2 * half] + b0;
                float x1 = acc[mt][nt][2 * half + 1] + b1;
                if (segid == 0) {
                    *(__nv_bfloat162*)(g_qh + (size_t)r * HD + lc) =
                        __float22bfloat162_rn(make_float2(x0, x1));
                } else if (segid == 3) {
                    *(float2*)(g_skip + (size_t)r * HIDD + lc) = make_float2(x0, x1);
                } else {
                    size_t off = (size_t)r * 1152 + (segid == 2 ? 576 : 0) + lc;
                    *(__nv_bfloat162*)(g_kvh + off) =
                        __float22bfloat162_rn(make_float2(x0, x1));
                }
            }
        }
    }
#undef LOAD_TILES
}

// ---------------- fused attention (R9 proven shape); last layer pools directly ----------------
__global__ void __launch_bounds__(192) attn_fused(int last) {
    __shared__ float red[NH][HIDD];
    int n = blockIdx.x;
    int wid = threadIdx.x >> 5, lane = threadIdx.x & 31;
    int half = lane >> 4, sub = lane & 15;
    int hb = wid * 48 + sub * 3;
    const __nv_bfloat162* kv2 = (const __nv_bfloat162*)g_kvh;   // row stride 576
    const __nv_bfloat162* q2  = (const __nv_bfloat162*)g_qh;    // row stride 288

    float q[6];
    ld6(q2 + (size_t)n * 288 + hb, q);

    int beg = g_rowptr[n], end = g_rowptr[n + 1];
    float m = -INFINITY, s = 0.f;
    float acc[6] = {0.f, 0.f, 0.f, 0.f, 0.f, 0.f};
    const float SC = 0.10206207261596577f;

    int i = beg;
    for (; i + 4 <= end; i += 4) {
        int s0 = __ldg(&g_srcs[i + half]);
        int s1 = __ldg(&g_srcs[i + 2 + half]);
        const __nv_bfloat162* k0 = kv2 + (size_t)s0 * 576 + hb;
        const __nv_bfloat162* k1 = kv2 + (size_t)s1 * 576 + hb;
        float p0 = dot6(q, k0);
        float p1 = dot6(q, k1);
#pragma unroll
        for (int off = 8; off > 0; off >>= 1) {
            p0 += __shfl_xor_sync(0xffffffffu, p0, off);
            p1 += __shfl_xor_sync(0xffffffffu, p1, off);
        }
        float v0[6], v1[6];
        ld6(k0 + 288, v0);
        ld6(k1 + 288, v1);
        float al0 = p0 * SC, al1 = p1 * SC;
        float mn = fmaxf(m, fmaxf(al0, al1));
        float corr = __expf(m - mn);
        float w0 = __expf(al0 - mn), w1 = __expf(al1 - mn);
#pragma unroll
        for (int j = 0; j < 6; j++)
            acc[j] = acc[j] * corr + w0 * v0[j] + w1 * v1[j];
        s = s * corr + w0 + w1;
        m = mn;
    }
    if (i + 2 <= end) {
        int s0 = __ldg(&g_srcs[i + half]);
        const __nv_bfloat162* k0 = kv2 + (size_t)s0 * 576 + hb;
        float p0 = dot6(q, k0);
#pragma unroll
        for (int off = 8; off > 0; off >>= 1)
            p0 += __shfl_xor_sync(0xffffffffu, p0, off);
        float v0[6];
        ld6(k0 + 288, v0);
        float al0 = p0 * SC;
        float mn = fmaxf(m, al0);
        float corr = __expf(m - mn);
        float w0 = __expf(al0 - mn);
#pragma unroll
        for (int j = 0; j < 6; j++)
            acc[j] = acc[j] * corr + w0 * v0[j];
        s = s * corr + w0;
        m = mn;
        i += 2;
    }
    if (i < end && half == 0) {
        int s0 = __ldg(&g_srcs[i]);
        const __nv_bfloat162* k0 = kv2 + (size_t)s0 * 576 + hb;
        float p0 = dot6(q, k0);
#pragma unroll
        for (int off = 8; off > 0; off >>= 1)
            p0 += __shfl_xor_sync(0x0000ffffu, p0, off);
        float v0[6];
        ld6(k0 + 288, v0);
        float al0 = p0 * SC;
        float mn = fmaxf(m, al0);
        float corr = __expf(m - mn);
        float w0 = __expf(al0 - mn);
#pragma unroll
        for (int j = 0; j < 6; j++)
            acc[j] = acc[j] * corr + w0 * v0[j];
        s = s * corr + w0;
        m = mn;
    }
    float mo = __shfl_xor_sync(0xffffffffu, m, 16);
    float Mn = fmaxf(m, mo);
    float f = (Mn == -INFINITY) ? 0.f : __expf(m - Mn);
    s *= f;
#pragma unroll
    for (int j = 0; j < 6; j++) acc[j] *= f;
    float s_tot = s + __shfl_xor_sync(0xffffffffu, s, 16);
    float at[6];
#pragma unroll
    for (int j = 0; j < 6; j++)
        at[j] = acc[j] + __shfl_xor_sync(0xffffffffu, acc[j], 16);
    float inv = (s_tot > 0.f) ? 1.f / (6.f * s_tot) : 0.f;
    if (half == 0) {
#pragma unroll
        for (int j = 0; j < 6; j++)
            red[wid][sub * 6 + j] = at[j] * inv;
    }
    __syncthreads();
    if (threadIdx.x < HIDD) {
        int d = threadIdx.x;
        float v = red[0][d] + red[1][d] + red[2][d] + red[3][d] + red[4][d] + red[5][d];
        v += g_skip[n * HIDD + d];
        v = fmaxf(v, 0.f);
        if (last)
            atomicAdd(&g_pool[g_batch[n] * HIDD + d], v);   // fused global-mean-pool sum
        else
            g_h[n * HIDD + d] = v;
    }
}

// ---------------- head ----------------
__global__ void head_kernel(const float* __restrict__ fc1w, const float* __restrict__ fc1b,
                            const float* __restrict__ fc2w, const float* __restrict__ fc2b) {
    int b = blockIdx.x, d = threadIdx.x;
    __shared__ float sg[96], st[96];
    __shared__ float snorm;
    float c = fmaxf((float)g_cnt[b], 1.f);
    sg[d] = g_pool[b * HIDD + d] / c;
    __syncthreads();
    float acc = fc1b[d];
    for (int i = 0; i < HIDD; i++) acc += sg[i] * fc1w[i * HIDD + d];
    st[d] = fmaxf(acc, 0.f);
    __syncthreads();
    acc = fc2b[d];
    for (int i = 0; i < HIDD; i++) acc += st[i] * fc2w[i * HIDD + d];
    float o = fmaxf(acc, 0.f);
    sg[d] = o * o;
    __syncthreads();
    if (d == 0) {
        float ss = 0.f;
        for (int i = 0; i < HIDD; i++) ss += sg[i];
        snorm = sqrtf(ss) + 1e-12f;
    }
    __syncthreads();
    g_gbuf[b * HIDD + d] = o / snorm;
}

__global__ void wn_kernel(const float* __restrict__ arcw) {
    int cIdx = blockIdx.x, d = threadIdx.x;
    __shared__ float sq[96];
    __shared__ float sn;
    float w = arcw[cIdx * HIDD + d];
    sq[d] = w * w;
    __syncthreads();
    if (d == 0) {
        float ss = 0.f;
        for (int i = 0; i < HIDD; i++) ss += sq[i];
        sn = sqrtf(ss) + 1e-12f;
    }
    __syncthreads();
    g_wn[cIdx * HIDD + d] = w / sn;
}

__global__ void out_kernel(float* __restrict__ out) {
    int t = blockIdx.x * blockDim.x + threadIdx.x;
    if (t >= NG * NCLS) return;
    int g = t / NCLS, c = t - g * NCLS;
    float acc = 0.f;
    for (int d = 0; d < HIDD; d++) acc += g_gbuf[g * HIDD + d] * g_wn[c * HIDD + d];
    out[t] = 30.f * acc;
}

// ---------------- driver ----------------
extern "C" void kernel_launch(void* const* d_in, const int* in_sizes, int n_in,
                              void* d_out, int out_size) {
    const float* x    = (const float*)d_in[0];
    const void*  ei   = d_in[1];
    const void*  bt   = d_in[2];
    const float* Wq1  = (const float*)d_in[3];
    const float* bq1  = (const float*)d_in[4];
    const float* Wk1  = (const float*)d_in[5];
    const float* bk1  = (const float*)d_in[6];
    const float* Wv1  = (const float*)d_in[7];
    const float* bv1  = (const float*)d_in[8];
    const float* Ws1  = (const float*)d_in[9];
    const float* bs1  = (const float*)d_in[10];
    const float* Wq_r = (const float*)d_in[11];
    const float* bq_r = (const float*)d_in[12];
    const float* Wk_r = (const float*)d_in[13];
    const float* bk_r = (const float*)d_in[14];
    const float* Wv_r = (const float*)d_in[15];
    const float* bv_r = (const float*)d_in[16];
    const float* Ws_r = (const float*)d_in[17];
    const float* bs_r = (const float*)d_in[18];
    const float* fc1w = (const float*)d_in[19];
    const float* fc1b = (const float*)d_in[20];
    const float* fc2w = (const float*)d_in[21];
    const float* fc2b = (const float*)d_in[22];
    const float* arcw = (const float*)d_in[23];
    float* out = (float*)d_out;

    void* hAddr = nullptr; void* wAddr = nullptr;
    cudaGetSymbolAddress(&hAddr, g_h);
    cudaGetSymbolAddress(&wAddr, g_Wtf);
    const float* hbuf = (const float*)hAddr;
    const float* wt   = (const float*)wAddr;

    dim3 ggrid(QC / BN, (NN + BM - 1) / BM);   // 19 x 157

    // fork a side stream for the CSR build; it overlaps wprep + layer-0 GEMM.
    // kernel_launch is called only for correctness + capture, so these host
    // objects are bounded (no device allocation).
    cudaStream_t s2;
    cudaEvent_t evFork, evJoin;
    cudaStreamCreateWithFlags(&s2, cudaStreamNonBlocking);
    cudaEventCreateWithFlags(&evFork, cudaEventDisableTiming);
    cudaEventCreateWithFlags(&evJoin, cudaEventDisableTiming);

    cudaEventRecord(evFork, 0);
    cudaStreamWaitEvent(s2, evFork, 0);

    // side stream: zero buffers + dtype, edges/batch/cnt, scan, scatter
    init_kernel<<<(NG * HIDD + 255) / 256, 256, 0, s2>>>((const unsigned*)ei);
    extract_all<<<(EE + 255) / 256, 256, 0, s2>>>(ei, bt);
    scan_kernel<<<1, 1024, 0, s2>>>();
    scatter_kernel<<<(EE + 255) / 256, 256, 0, s2>>>();
    cudaEventRecord(evJoin, s2);

    // main stream: weight prep + layer-0 GEMM (independent of CSR)
    wprep<<<dim3(57, 4, 5), dim3(32, 8)>>>(Wq1, Wk1, Wv1, Ws1, Wq_r, Wk_r, Wv_r, Ws_r);
    gemm_tc<<<ggrid, 128>>>(x, IND, wt, bq1, bk1, bv1, bs1);

    cudaStreamWaitEvent(0, evJoin, 0);
    attn_fused<<<NN, 192>>>(0);

    for (int l = 1; l < 5; l++) {
        int i = l - 1;
        const float* wl = wt + (size_t)1824 * 128 + (size_t)i * 1824 * 96;
        gemm_tc<<<ggrid, 128>>>(hbuf, HIDD, wl,
                                bq_r + (size_t)i * HD, bk_r + (size_t)i * HD,
                                bv_r + (size_t)i * HD, bs_r + (size_t)i * HIDD);
        attn_fused<<<NN, 192>>>(l == 4 ? 1 : 0);
    }

    head_kernel<<<NG, HIDD>>>(fc1w, fc1b, fc2w, fc2b);
    wn_kernel<<<NCLS, HIDD>>>(arcw);
    out_kernel<<<(NG * NCLS + 255) / 256, 256>>>(out);
}